// round 4
// baseline (speedup 1.0000x reference)
#include <cuda_runtime.h>

// Problem constants
#define NSITES   50000
#define NPERM    12
#define NNEIGH   8
#define NODEF    64
#define INF      512
#define OUTF     64
#define LN2F     0.6931471805599453f

// Tiling
#define BM       96          // rows per block = 8 sites * 12 perms
#define SITES_PB 8
#define NTHREADS 384
#define LDA      68          // padded A row stride in floats (17 float4)

// k-major transposed weights: g_Wt[k][o] = W[o][k]
__device__ float g_Wt[INF * OUTF];

__global__ void transpose_W_kernel(const float* __restrict__ W) {
    int i = blockIdx.x * blockDim.x + threadIdx.x;   // over 32768
    if (i < INF * OUTF) {
        int k = i >> 6;        // 0..511
        int o = i & 63;        // 0..63
        g_Wt[i] = W[o * INF + k];
    }
}

__global__ __launch_bounds__(NTHREADS)
void lcnn_main_kernel(const float* __restrict__ X,
                      const int*   __restrict__ NS,
                      const float* __restrict__ bias,
                      float*       __restrict__ out)
{
    __shared__ float A_sm[BM * LDA];       // 96*68*4 = 26112 B (reused as reduce buf)
    __shared__ float W_sm[64 * 64];        // 16384 B
    __shared__ int   idx_sm[BM * NNEIGH];  // 3072 B
    __shared__ float b_sm[OUTF];           // 256 B

    const int tid = threadIdx.x;
    const int blk = blockIdx.x;
    const long row_base = (long)blk * BM;  // global (site,perm) row

    // Load all neighbor indices for this block's 96 rows (coalesced)
    for (int i = tid; i < BM * NNEIGH; i += NTHREADS)
        idx_sm[i] = NS[row_base * NNEIGH + i];
    if (tid < OUTF) b_sm[tid] = bias[tid];

    const int tx = tid & 15;   // 0..15 : output-col group (4 cols each)
    const int ty = tid >> 4;   // 0..23 : row group (4 rows each)

    float acc[4][4];
    #pragma unroll
    for (int r = 0; r < 4; r++)
        #pragma unroll
        for (int c2 = 0; c2 < 4; c2++)
            acc[r][c2] = 0.0f;

    const float4* X4  = (const float4*)X;
    const float4* Wt4 = (const float4*)g_Wt;
    float4* A4 = (float4*)A_sm;   // row stride 17 float4
    float4* W4 = (float4*)W_sm;

    // K loop: 8 chunks of 64 (one neighbor slot per chunk)
    for (int c = 0; c < NNEIGH; c++) {
        __syncthreads();

        // Stage A: 96 rows x 16 float4 gathered rows (1536 float4, 4/thread)
        #pragma unroll
        for (int it = 0; it < 4; it++) {
            int linear = tid + it * NTHREADS;       // < 1536
            int m = linear >> 4;
            int f = linear & 15;
            int nb = idx_sm[m * NNEIGH + c];
            A4[m * 17 + f] = X4[(long)nb * 16 + f];
        }
        // Stage W chunk: k-major [64][64] direct copy (1024 float4)
        for (int linear = tid; linear < 1024; linear += NTHREADS) {
            W4[linear] = Wt4[c * 1024 + linear];
        }
        __syncthreads();

        // Register-tiled FMA: 16 FMA per (4 LDS.32 + 1 LDS.128)
        #pragma unroll 4
        for (int k = 0; k < 64; k++) {
            float4 w = W4[k * 16 + tx];
            float a0 = A_sm[(ty * 4 + 0) * LDA + k];
            float a1 = A_sm[(ty * 4 + 1) * LDA + k];
            float a2 = A_sm[(ty * 4 + 2) * LDA + k];
            float a3 = A_sm[(ty * 4 + 3) * LDA + k];
            acc[0][0] += a0 * w.x; acc[0][1] += a0 * w.y;
            acc[0][2] += a0 * w.z; acc[0][3] += a0 * w.w;
            acc[1][0] += a1 * w.x; acc[1][1] += a1 * w.y;
            acc[1][2] += a1 * w.z; acc[1][3] += a1 * w.w;
            acc[2][0] += a2 * w.x; acc[2][1] += a2 * w.y;
            acc[2][2] += a2 * w.z; acc[2][3] += a2 * w.w;
            acc[3][0] += a3 * w.x; acc[3][1] += a3 * w.y;
            acc[3][2] += a3 * w.z; acc[3][3] += a3 * w.w;
        }
    }

    // Epilogue: bias + shifted-softplus, partial sum over this thread's 4 perms.
    // Each thread's 4 rows (ty*4 .. ty*4+3) lie inside ONE site (4 | 12 pattern).
    float part[4];
    #pragma unroll
    for (int c2 = 0; c2 < 4; c2++) {
        float bv = b_sm[tx * 4 + c2];
        float s = 0.0f;
        #pragma unroll
        for (int r = 0; r < 4; r++) {
            float x = acc[r][c2] + bv;
            // stable softplus
            float sp = fmaxf(x, 0.0f) + __logf(1.0f + __expf(-fabsf(x)));
            s += sp - LN2F;
        }
        part[c2] = s;
    }

    __syncthreads();            // done with A_sm as GEMM tile
    float* red = A_sm;          // reuse: [24][64] partials
    #pragma unroll
    for (int c2 = 0; c2 < 4; c2++)
        red[ty * 64 + tx * 4 + c2] = part[c2];
    __syncthreads();

    // Combine 3 ty-groups per site (perms 0-3, 4-7, 8-11); coalesced store.
    // 512 outputs per block, 384 threads -> strided loop (NOT a single guard!).
    for (int i = tid; i < SITES_PB * OUTF; i += NTHREADS) {
        int s   = i >> 6;
        int col = i & 63;
        float v = red[(3 * s + 0) * 64 + col]
                + red[(3 * s + 1) * 64 + col]
                + red[(3 * s + 2) * 64 + col];
        out[((long)blk * SITES_PB + s) * OUTF + col] = v;
    }
}

extern "C" void kernel_launch(void* const* d_in, const int* in_sizes, int n_in,
                              void* d_out, int out_size) {
    const float* X  = (const float*)d_in[0];   // X_sites (50000,64) f32
    const int*   NS = (const int*)  d_in[1];   // X_NSs   (50000,12,8) i32
    const float* W  = (const float*)d_in[2];   // W       (64,512) f32
    const float* b  = (const float*)d_in[3];   // b       (64,) f32
    float* out = (float*)d_out;                // (50000,64) f32

    transpose_W_kernel<<<(INF * OUTF + 255) / 256, 256>>>(W);
    lcnn_main_kernel<<<NSITES / SITES_PB, NTHREADS>>>(X, NS, b, out);
}